// round 1
// baseline (speedup 1.0000x reference)
#include <cuda_runtime.h>

#define NPL   50000
#define L_TOT 6
#define KN    8
#define FEAT  32
#define H     128
#define MT    28      // nodes per block
#define NT    128     // threads per block == H

// One dense stage: sO[m][t] = tanh(b[t] + sum_k sX[m][k]*W[k][t] (+ sum_k sY[m][k]*W2[k][t]))
// thread t owns output feature t; activations read from shared (broadcast LDS.128).
template<bool CAT>
__device__ __forceinline__ void stage(
    const float* __restrict__ sX, const float* __restrict__ sY,
    const float* __restrict__ W,  const float* __restrict__ b,
    float* __restrict__ sO, int t)
{
    float acc[MT];
    float bias = b[t];
#pragma unroll
    for (int m = 0; m < MT; m++) acc[m] = bias;

#pragma unroll 2
    for (int k = 0; k < H; k += 4) {
        float w0 = W[(k+0)*H + t];
        float w1 = W[(k+1)*H + t];
        float w2 = W[(k+2)*H + t];
        float w3 = W[(k+3)*H + t];
#pragma unroll
        for (int m = 0; m < MT; m++) {
            float4 a = *reinterpret_cast<const float4*>(sX + m*H + k);
            acc[m] = fmaf(a.x, w0, acc[m]);
            acc[m] = fmaf(a.y, w1, acc[m]);
            acc[m] = fmaf(a.z, w2, acc[m]);
            acc[m] = fmaf(a.w, w3, acc[m]);
        }
    }
    if (CAT) {
        const float* __restrict__ W2 = W + H * H;
#pragma unroll 2
        for (int k = 0; k < H; k += 4) {
            float w0 = W2[(k+0)*H + t];
            float w1 = W2[(k+1)*H + t];
            float w2 = W2[(k+2)*H + t];
            float w3 = W2[(k+3)*H + t];
#pragma unroll
            for (int m = 0; m < MT; m++) {
                float4 a = *reinterpret_cast<const float4*>(sY + m*H + k);
                acc[m] = fmaf(a.x, w0, acc[m]);
                acc[m] = fmaf(a.y, w1, acc[m]);
                acc[m] = fmaf(a.z, w2, acc[m]);
                acc[m] = fmaf(a.w, w3, acc[m]);
            }
        }
    }
#pragma unroll
    for (int m = 0; m < MT; m++) sO[m*H + t] = tanhf(acc[m]);
}

// base = tanh(nf @ W_embed + b_embed) for all nodes -> written straight into emb (= d_out)
__global__ void __launch_bounds__(NT)
embed_kernel(const float* __restrict__ nf, const float* __restrict__ W,
             const float* __restrict__ b, float* __restrict__ out, int n_nodes)
{
    __shared__ float s_nf[MT * FEAT];
    int t    = threadIdx.x;
    int base = blockIdx.x * MT;

    for (int i = t; i < MT * FEAT; i += NT) {
        int m = i / FEAT, k = i % FEAT;
        int row = base + m;
        if (row >= n_nodes) row = n_nodes - 1;
        s_nf[m * FEAT + k] = nf[(long)row * FEAT + k];
    }
    __syncthreads();

    float acc[MT];
    float bias = b[t];
#pragma unroll
    for (int m = 0; m < MT; m++) acc[m] = bias;

#pragma unroll 2
    for (int k = 0; k < FEAT; k += 4) {
        float w0 = W[(k+0)*H + t];
        float w1 = W[(k+1)*H + t];
        float w2 = W[(k+2)*H + t];
        float w3 = W[(k+3)*H + t];
#pragma unroll
        for (int m = 0; m < MT; m++) {
            float4 a = *reinterpret_cast<const float4*>(s_nf + m*FEAT + k);
            acc[m] = fmaf(a.x, w0, acc[m]);
            acc[m] = fmaf(a.y, w1, acc[m]);
            acc[m] = fmaf(a.z, w2, acc[m]);
            acc[m] = fmaf(a.w, w3, acc[m]);
        }
    }
#pragma unroll
    for (int m = 0; m < MT; m++) {
        int row = base + m;
        if (row < n_nodes) out[(long)row * H + t] = tanhf(acc[m]);
    }
}

// One full GNN layer for layer l: gather(K=8) -> 11 fused dense-tanh stages -> write emb block l.
__global__ void __launch_bounds__(NT)
layer_kernel(float* emb,
             const int* __restrict__ src, int l,
             const float* __restrict__ Wmp0, const float* __restrict__ bmp0,
             const float* __restrict__ Wmp1, const float* __restrict__ bmp1,
             const float* __restrict__ Wmpc, const float* __restrict__ bmpc,
             const float* __restrict__ Wne0, const float* __restrict__ bne0,
             const float* __restrict__ Wne1, const float* __restrict__ bne1,
             const float* __restrict__ Wnec, const float* __restrict__ bnec)
{
    __shared__ float A[MT * H];
    __shared__ float B[MT * H];
    __shared__ float C[MT * H];
    __shared__ int   sidx[MT * KN];

    int t  = threadIdx.x;
    int d0 = blockIdx.x * MT;

    // edge indices for this block's nodes (clamped tail)
    const int* __restrict__ srcL = src + (long)(l - 1) * NPL * KN;
    for (int i = t; i < MT * KN; i += NT) {
        int node = d0 + i / KN;
        if (node >= NPL) node = NPL - 1;
        sidx[i] = srcL[(long)node * KN + (i % KN)];
    }
    __syncthreads();

    // gather: msgs[m][t] = sum over 8 neighbors of prev-layer embedding (src values are global rows)
#pragma unroll 1
    for (int m = 0; m < MT; m++) {
        float s = 0.f;
#pragma unroll
        for (int k = 0; k < KN; k++) {
            int row = sidx[m * KN + k];
            s += emb[(long)row * H + t];
        }
        A[m * H + t] = s;
    }
    __syncthreads();

    // message-passing MLP
    stage<false>(A, nullptr, Wmp0, bmp0, B, t); __syncthreads();        // r0 -> B
    stage<false>(B, nullptr, Wmp1, bmp1, C, t); __syncthreads();        // r  -> C
    stage<true >(C, B, Wmpc + 0*2*H*H, bmpc + 0*H, A, t); __syncthreads();
    stage<true >(A, B, Wmpc + 1*2*H*H, bmpc + 1*H, C, t); __syncthreads();
    stage<true >(C, B, Wmpc + 2*2*H*H, bmpc + 2*H, A, t); __syncthreads();
    stage<true >(A, B, Wmpc + 3*2*H*H, bmpc + 3*H, C, t); __syncthreads();   // r -> C

    // blk (this layer's base embedding) -> A
#pragma unroll 1
    for (int m = 0; m < MT; m++) {
        int node = d0 + m;
        if (node >= NPL) node = NPL - 1;
        A[m * H + t] = emb[(long)(l * NPL + node) * H + t];
    }
    __syncthreads();

    // node-embedding MLP
    stage<true >(A, C, Wne0, bne0, B, t); __syncthreads();              // c0 -> B
    stage<false>(B, nullptr, Wne1, bne1, A, t); __syncthreads();        // e  -> A
    stage<true >(A, B, Wnec + 0*2*H*H, bnec + 0*H, C, t); __syncthreads();
    stage<true >(C, B, Wnec + 1*2*H*H, bnec + 1*H, A, t); __syncthreads();
    stage<true >(A, B, Wnec + 2*2*H*H, bnec + 2*H, C, t); __syncthreads();
    stage<true >(C, B, Wnec + 3*2*H*H, bnec + 3*H, A, t); __syncthreads();   // e -> A

#pragma unroll 1
    for (int m = 0; m < MT; m++) {
        int node = d0 + m;
        if (node < NPL) emb[(long)(l * NPL + node) * H + t] = A[m * H + t];
    }
}

extern "C" void kernel_launch(void* const* d_in, const int* in_sizes, int n_in,
                              void* d_out, int out_size)
{
    // metadata order:
    // 0 node_feats, 1 src, 2 dst, 3 W_embed, 4 b_embed, 5 W_mp0, 6 b_mp0,
    // 7 W_mp1, 8 b_mp1, 9 W_mp_cat, 10 b_mp_cat, 11 W_ne0, 12 b_ne0,
    // 13 W_ne1, 14 b_ne1, 15 W_ne_cat, 16 b_ne_cat
    const float* nf      = (const float*)d_in[0];
    const int*   src     = (const int*)  d_in[1];
    const float* W_embed = (const float*)d_in[3];
    const float* b_embed = (const float*)d_in[4];
    const float* W_mp0   = (const float*)d_in[5];
    const float* b_mp0   = (const float*)d_in[6];
    const float* W_mp1   = (const float*)d_in[7];
    const float* b_mp1   = (const float*)d_in[8];
    const float* W_mpc   = (const float*)d_in[9];
    const float* b_mpc   = (const float*)d_in[10];
    const float* W_ne0   = (const float*)d_in[11];
    const float* b_ne0   = (const float*)d_in[12];
    const float* W_ne1   = (const float*)d_in[13];
    const float* b_ne1   = (const float*)d_in[14];
    const float* W_nec   = (const float*)d_in[15];
    const float* b_nec   = (const float*)d_in[16];

    float* out = (float*)d_out;

    const int n_nodes = L_TOT * NPL;  // 300000
    embed_kernel<<<(n_nodes + MT - 1) / MT, NT>>>(nf, W_embed, b_embed, out, n_nodes);

    const int layer_blocks = (NPL + MT - 1) / MT;
    for (int l = 1; l < L_TOT; l++) {
        layer_kernel<<<layer_blocks, NT>>>(out, src, l,
                                           W_mp0, b_mp0, W_mp1, b_mp1, W_mpc, b_mpc,
                                           W_ne0, b_ne0, W_ne1, b_ne1, W_nec, b_nec);
    }
}

// round 2
// speedup vs baseline: 1.4762x; 1.4762x over previous
#include <cuda_runtime.h>

#define NPL   50000
#define L_TOT 6
#define KN    8
#define FEAT  32
#define H     128
#define MT    32      // nodes per block (4 warps x 8)
#define NT    128
#define MW    8       // nodes per warp

typedef unsigned long long ull;

__device__ __forceinline__ ull pack2(float x, float y) {
    ull r; asm("mov.b64 %0, {%1, %2};" : "=l"(r) : "f"(x), "f"(y)); return r;
}
__device__ __forceinline__ void fma2(ull& acc, ull a, ull b) {
    asm("fma.rn.f32x2 %0, %1, %2, %0;" : "+l"(acc) : "l"(a), "l"(b));
}
__device__ __forceinline__ float2 unpack2(ull v) {
    float2 f; asm("mov.b64 {%0, %1}, %2;" : "=f"(f.x), "=f"(f.y) : "l"(v)); return f;
}

// Accumulate acc[m][.] += sX[m0+m][:] @ W[:, f..f+3]  (K = H)
// lane owns 4 output features (2 packed pairs), warp owns 8 nodes.
__device__ __forceinline__ void accum(const float* __restrict__ sX,
                                      const float* __restrict__ W,
                                      int f, int m0, ull acc[MW][2])
{
#pragma unroll 2
    for (int k = 0; k < H; k += 4) {
        float4 w0 = *reinterpret_cast<const float4*>(W + (k+0)*H + f);
        float4 w1 = *reinterpret_cast<const float4*>(W + (k+1)*H + f);
        float4 w2 = *reinterpret_cast<const float4*>(W + (k+2)*H + f);
        float4 w3 = *reinterpret_cast<const float4*>(W + (k+3)*H + f);
        ull w0a = pack2(w0.x, w0.y), w0b = pack2(w0.z, w0.w);
        ull w1a = pack2(w1.x, w1.y), w1b = pack2(w1.z, w1.w);
        ull w2a = pack2(w2.x, w2.y), w2b = pack2(w2.z, w2.w);
        ull w3a = pack2(w3.x, w3.y), w3b = pack2(w3.z, w3.w);
#pragma unroll
        for (int m = 0; m < MW; m++) {
            float4 a = *reinterpret_cast<const float4*>(sX + (m0 + m)*H + k);
            ull ax = pack2(a.x, a.x);
            fma2(acc[m][0], ax, w0a); fma2(acc[m][1], ax, w0b);
            ull ay = pack2(a.y, a.y);
            fma2(acc[m][0], ay, w1a); fma2(acc[m][1], ay, w1b);
            ull az = pack2(a.z, a.z);
            fma2(acc[m][0], az, w2a); fma2(acc[m][1], az, w2b);
            ull aw = pack2(a.w, a.w);
            fma2(acc[m][0], aw, w3a); fma2(acc[m][1], aw, w3b);
        }
    }
}

// One dense stage: sO[m][f] = tanh(b[f] + sX[m] @ W (+ sY[m] @ W2))
template<bool CAT>
__device__ __forceinline__ void stage(const float* __restrict__ sX,
                                      const float* __restrict__ sY,
                                      const float* __restrict__ W,
                                      const float* __restrict__ b,
                                      float* __restrict__ sO, int f, int m0)
{
    ull acc[MW][2];
    float4 bb = *reinterpret_cast<const float4*>(b + f);
    ull b01 = pack2(bb.x, bb.y), b23 = pack2(bb.z, bb.w);
#pragma unroll
    for (int m = 0; m < MW; m++) { acc[m][0] = b01; acc[m][1] = b23; }

    accum(sX, W, f, m0, acc);
    if (CAT) accum(sY, W + H*H, f, m0, acc);

#pragma unroll
    for (int m = 0; m < MW; m++) {
        float2 p = unpack2(acc[m][0]);
        float2 q = unpack2(acc[m][1]);
        float4 o;
        o.x = tanhf(p.x); o.y = tanhf(p.y); o.z = tanhf(q.x); o.w = tanhf(q.y);
        *reinterpret_cast<float4*>(sO + (m0 + m)*H + f) = o;
    }
}

// base = tanh(nf @ W_embed + b_embed), written into emb (= d_out)
__global__ void __launch_bounds__(NT)
embed_kernel(const float* __restrict__ nf, const float* __restrict__ W,
             const float* __restrict__ b, float* __restrict__ out, int n_nodes)
{
    __shared__ float s_nf[MT * FEAT];
    int t    = threadIdx.x;
    int lane = t & 31;
    int wrp  = t >> 5;
    int f    = 4 * lane;
    int m0   = wrp * MW;
    int base = blockIdx.x * MT;

    for (int i = t; i < MT * FEAT; i += NT) {
        int m = i / FEAT, k = i % FEAT;
        int row = base + m;
        if (row >= n_nodes) row = n_nodes - 1;
        s_nf[m * FEAT + k] = nf[(long)row * FEAT + k];
    }
    __syncthreads();

    ull acc[MW][2];
    float4 bb = *reinterpret_cast<const float4*>(b + f);
    ull b01 = pack2(bb.x, bb.y), b23 = pack2(bb.z, bb.w);
#pragma unroll
    for (int m = 0; m < MW; m++) { acc[m][0] = b01; acc[m][1] = b23; }

#pragma unroll 2
    for (int k = 0; k < FEAT; k += 4) {
        float4 w0 = *reinterpret_cast<const float4*>(W + (k+0)*H + f);
        float4 w1 = *reinterpret_cast<const float4*>(W + (k+1)*H + f);
        float4 w2 = *reinterpret_cast<const float4*>(W + (k+2)*H + f);
        float4 w3 = *reinterpret_cast<const float4*>(W + (k+3)*H + f);
        ull w0a = pack2(w0.x, w0.y), w0b = pack2(w0.z, w0.w);
        ull w1a = pack2(w1.x, w1.y), w1b = pack2(w1.z, w1.w);
        ull w2a = pack2(w2.x, w2.y), w2b = pack2(w2.z, w2.w);
        ull w3a = pack2(w3.x, w3.y), w3b = pack2(w3.z, w3.w);
#pragma unroll
        for (int m = 0; m < MW; m++) {
            float4 a = *reinterpret_cast<const float4*>(s_nf + (m0+m)*FEAT + k);
            ull ax = pack2(a.x, a.x);
            fma2(acc[m][0], ax, w0a); fma2(acc[m][1], ax, w0b);
            ull ay = pack2(a.y, a.y);
            fma2(acc[m][0], ay, w1a); fma2(acc[m][1], ay, w1b);
            ull az = pack2(a.z, a.z);
            fma2(acc[m][0], az, w2a); fma2(acc[m][1], az, w2b);
            ull aw = pack2(a.w, a.w);
            fma2(acc[m][0], aw, w3a); fma2(acc[m][1], aw, w3b);
        }
    }
#pragma unroll
    for (int m = 0; m < MW; m++) {
        int row = base + m0 + m;
        if (row < n_nodes) {
            float2 p = unpack2(acc[m][0]);
            float2 q = unpack2(acc[m][1]);
            float4 o;
            o.x = tanhf(p.x); o.y = tanhf(p.y); o.z = tanhf(q.x); o.w = tanhf(q.y);
            *reinterpret_cast<float4*>(out + (long)row * H + f) = o;
        }
    }
}

// Full GNN layer l: gather(K=8) -> 11 fused dense-tanh stages -> write emb block l.
__global__ void __launch_bounds__(NT)
layer_kernel(float* emb,
             const int* __restrict__ src, int l,
             const float* __restrict__ Wmp0, const float* __restrict__ bmp0,
             const float* __restrict__ Wmp1, const float* __restrict__ bmp1,
             const float* __restrict__ Wmpc, const float* __restrict__ bmpc,
             const float* __restrict__ Wne0, const float* __restrict__ bne0,
             const float* __restrict__ Wne1, const float* __restrict__ bne1,
             const float* __restrict__ Wnec, const float* __restrict__ bnec)
{
    __shared__ float A[MT * H];
    __shared__ float B[MT * H];
    __shared__ float C[MT * H];
    __shared__ int   sidx[MT * KN];

    int t    = threadIdx.x;
    int lane = t & 31;
    int wrp  = t >> 5;
    int f    = 4 * lane;
    int m0   = wrp * MW;
    int d0   = blockIdx.x * MT;

    const int* __restrict__ srcL = src + (long)(l - 1) * NPL * KN;
    for (int i = t; i < MT * KN; i += NT) {
        int node = d0 + i / KN;
        if (node >= NPL) node = NPL - 1;
        sidx[i] = srcL[(long)node * KN + (i % KN)];
    }
    __syncthreads();

    // gather: A[m][f..f+3] = sum over 8 neighbors (src rows are global)
#pragma unroll
    for (int m = 0; m < MW; m++) {
        float4 s = make_float4(0.f, 0.f, 0.f, 0.f);
#pragma unroll
        for (int k = 0; k < KN; k++) {
            int row = sidx[(m0 + m) * KN + k];
            float4 v = *reinterpret_cast<const float4*>(emb + (long)row * H + f);
            s.x += v.x; s.y += v.y; s.z += v.z; s.w += v.w;
        }
        *reinterpret_cast<float4*>(A + (m0 + m) * H + f) = s;
    }
    __syncthreads();

    // message-passing MLP
    stage<false>(A, nullptr, Wmp0, bmp0, B, f, m0); __syncthreads();      // r0 -> B
    stage<false>(B, nullptr, Wmp1, bmp1, C, f, m0); __syncthreads();      // r  -> C
    stage<true >(C, B, Wmpc + 0*2*H*H, bmpc + 0*H, A, f, m0); __syncthreads();
    stage<true >(A, B, Wmpc + 1*2*H*H, bmpc + 1*H, C, f, m0); __syncthreads();
    stage<true >(C, B, Wmpc + 2*2*H*H, bmpc + 2*H, A, f, m0); __syncthreads();
    stage<true >(A, B, Wmpc + 3*2*H*H, bmpc + 3*H, C, f, m0); __syncthreads();  // r -> C

    // this layer's base embedding -> A
#pragma unroll
    for (int m = 0; m < MW; m++) {
        int node = d0 + m0 + m;
        if (node >= NPL) node = NPL - 1;
        *reinterpret_cast<float4*>(A + (m0 + m) * H + f) =
            *reinterpret_cast<const float4*>(emb + (long)(l * NPL + node) * H + f);
    }
    __syncthreads();

    // node-embedding MLP
    stage<true >(A, C, Wne0, bne0, B, f, m0); __syncthreads();            // c0 -> B
    stage<false>(B, nullptr, Wne1, bne1, A, f, m0); __syncthreads();      // e  -> A
    stage<true >(A, B, Wnec + 0*2*H*H, bnec + 0*H, C, f, m0); __syncthreads();
    stage<true >(C, B, Wnec + 1*2*H*H, bnec + 1*H, A, f, m0); __syncthreads();
    stage<true >(A, B, Wnec + 2*2*H*H, bnec + 2*H, C, f, m0); __syncthreads();
    stage<true >(C, B, Wnec + 3*2*H*H, bnec + 3*H, A, f, m0); __syncthreads();  // e -> A

#pragma unroll
    for (int m = 0; m < MW; m++) {
        int node = d0 + m0 + m;
        if (node < NPL)
            *reinterpret_cast<float4*>(emb + (long)(l * NPL + node) * H + f) =
                *reinterpret_cast<const float4*>(A + (m0 + m) * H + f);
    }
}

extern "C" void kernel_launch(void* const* d_in, const int* in_sizes, int n_in,
                              void* d_out, int out_size)
{
    const float* nf      = (const float*)d_in[0];
    const int*   src     = (const int*)  d_in[1];
    const float* W_embed = (const float*)d_in[3];
    const float* b_embed = (const float*)d_in[4];
    const float* W_mp0   = (const float*)d_in[5];
    const float* b_mp0   = (const float*)d_in[6];
    const float* W_mp1   = (const float*)d_in[7];
    const float* b_mp1   = (const float*)d_in[8];
    const float* W_mpc   = (const float*)d_in[9];
    const float* b_mpc   = (const float*)d_in[10];
    const float* W_ne0   = (const float*)d_in[11];
    const float* b_ne0   = (const float*)d_in[12];
    const float* W_ne1   = (const float*)d_in[13];
    const float* b_ne1   = (const float*)d_in[14];
    const float* W_nec   = (const float*)d_in[15];
    const float* b_nec   = (const float*)d_in[16];

    float* out = (float*)d_out;

    const int n_nodes = L_TOT * NPL;
    embed_kernel<<<(n_nodes + MT - 1) / MT, NT>>>(nf, W_embed, b_embed, out, n_nodes);

    const int layer_blocks = (NPL + MT - 1) / MT;
    for (int l = 1; l < L_TOT; l++) {
        layer_kernel<<<layer_blocks, NT>>>(out, src, l,
                                           W_mp0, b_mp0, W_mp1, b_mp1, W_mpc, b_mpc,
                                           W_ne0, b_ne0, W_ne1, b_ne1, W_nec, b_nec);
    }
}